// round 8
// baseline (speedup 1.0000x reference)
#include <cuda_runtime.h>
#include <cuda_bf16.h>

// WeightAndSum: gated segment sum. Single-wave persistent layout, 4-row
// groups, depth-2 software pipeline. NO output zeroing: each segment's owner
// warp (the one holding the segment's first row) writes its partial with a
// plain vector STORE (overwrites harness poison); warps that start mid-segment
// defer their leading partial and atomicAdd it after a grid arrival barrier.
//   logits = feats @ W + b   (atom logits output, pre-sigmoid)
//   out[g] = sum_{seg[r]==g} sigmoid(logit_r) * feats[r]

#define F_DIM 128
#define F_VEC 32          // float4s per row

__device__ int g_arrive = 0;   // blocks past main loop (stores visible)
__device__ int g_done   = 0;   // blocks fully finished (for counter reset)

__global__ __launch_bounds__(256, 3)
void was_kernel(
    // atom job
    const float* __restrict__ a_feats, const float* __restrict__ a_W,
    const float* __restrict__ a_b, const int* __restrict__ a_seg,
    float* __restrict__ a_out, float* __restrict__ a_logits,
    int a_n, int a_rpw, int a_blocks,
    // vir job
    const float* __restrict__ v_feats, const float* __restrict__ v_W,
    const float* __restrict__ v_b, const int* __restrict__ v_seg,
    float* __restrict__ v_out,
    int v_n, int v_rpw)
{
    const int total_blocks = gridDim.x;

    const float* feats;
    const float* Wp;
    const float* bp;
    const int*   seg;
    float*       outp;
    float*       logits;
    int n, rpw, block_in_job;

    if (blockIdx.x < (unsigned)a_blocks) {
        feats = a_feats; Wp = a_W; bp = a_b; seg = a_seg;
        outp = a_out; logits = a_logits; n = a_n; rpw = a_rpw;
        block_in_job = blockIdx.x;
    } else {
        feats = v_feats; Wp = v_W; bp = v_b; seg = v_seg;
        outp = v_out; logits = nullptr; n = v_n; rpw = v_rpw;
        block_in_job = blockIdx.x - a_blocks;
    }

    const int lane  = threadIdx.x & 31;
    const int gwarp = block_in_job * (blockDim.x >> 5) + (threadIdx.x >> 5);

    long start = (long)gwarp * rpw;          // rpw is a multiple of 4
    bool active = (start < n);

    // Deferred (boundary-in) partial: this warp's chunk starts mid-segment.
    bool   have_def = false;
    int    def_seg  = 0;
    float4 def_acc  = make_float4(0.f, 0.f, 0.f, 0.f);

    if (active) {
        long end = start + rpw;
        if (end > n) end = n;                // n is a multiple of 4

        const float4 Wv  = reinterpret_cast<const float4*>(Wp)[lane];
        const float bias = bp[0];
        const float4* frows = reinterpret_cast<const float4*>(feats);

        float4 acc = make_float4(0.f, 0.f, 0.f, 0.f);
        int cur_seg = __ldg(&seg[start]);
        // Does our first segment continue from the previous chunk?
        bool first_inherited =
            (start > 0) && (__ldg(&seg[start - 1]) == cur_seg);

        // depth-2 pipeline: prefetch first 4-row group
        float4 f0 = __ldcs(&frows[(start + 0) * F_VEC + lane]);
        float4 f1 = __ldcs(&frows[(start + 1) * F_VEC + lane]);
        float4 f2 = __ldcs(&frows[(start + 2) * F_VEC + lane]);
        float4 f3 = __ldcs(&frows[(start + 3) * F_VEC + lane]);
        int4  sv  = *reinterpret_cast<const int4*>(seg + start);

        for (long r = start; r < end; r += 4) {
            float4 g0, g1, g2, g3;
            int4 sn;
            if (r + 4 < end) {
                g0 = __ldcs(&frows[(r + 4) * F_VEC + lane]);
                g1 = __ldcs(&frows[(r + 5) * F_VEC + lane]);
                g2 = __ldcs(&frows[(r + 6) * F_VEC + lane]);
                g3 = __ldcs(&frows[(r + 7) * F_VEC + lane]);
                sn = *reinterpret_cast<const int4*>(seg + r + 4);
            }

            float p0 = f0.x * Wv.x + f0.y * Wv.y + f0.z * Wv.z + f0.w * Wv.w;
            float p1 = f1.x * Wv.x + f1.y * Wv.y + f1.z * Wv.z + f1.w * Wv.w;
            float p2 = f2.x * Wv.x + f2.y * Wv.y + f2.z * Wv.z + f2.w * Wv.w;
            float p3 = f3.x * Wv.x + f3.y * Wv.y + f3.z * Wv.z + f3.w * Wv.w;

            #pragma unroll
            for (int d = 16; d > 0; d >>= 1) {
                p0 += __shfl_xor_sync(0xFFFFFFFFu, p0, d);
                p1 += __shfl_xor_sync(0xFFFFFFFFu, p1, d);
                p2 += __shfl_xor_sync(0xFFFFFFFFu, p2, d);
                p3 += __shfl_xor_sync(0xFFFFFFFFu, p3, d);
            }

            float l0 = p0 + bias, l1 = p1 + bias, l2 = p2 + bias, l3 = p3 + bias;

            if (logits != nullptr && lane == 0) {
                __stcs(reinterpret_cast<float4*>(logits + r),
                       make_float4(l0, l1, l2, l3));
            }

            float w0 = 1.0f / (1.0f + __expf(-l0));
            float w1 = 1.0f / (1.0f + __expf(-l1));
            float w2 = 1.0f / (1.0f + __expf(-l2));
            float w3 = 1.0f / (1.0f + __expf(-l3));

            #pragma unroll
            for (int k = 0; k < 4; ++k) {
                int s     = (k == 0) ? sv.x : (k == 1) ? sv.y : (k == 2) ? sv.z : sv.w;
                float w   = (k == 0) ? w0   : (k == 1) ? w1   : (k == 2) ? w2   : w3;
                float4 f  = (k == 0) ? f0   : (k == 1) ? f1   : (k == 2) ? f2   : f3;
                if (s != cur_seg) {
                    if (first_inherited) {
                        def_acc = acc; def_seg = cur_seg; have_def = true;
                        first_inherited = false;
                    } else {
                        // owner flush: plain vector store (poison overwrite)
                        *reinterpret_cast<float4*>(
                            outp + (long)cur_seg * F_DIM + lane * 4) = acc;
                    }
                    acc = make_float4(0.f, 0.f, 0.f, 0.f);
                    cur_seg = s;
                }
                acc.x += w * f.x;
                acc.y += w * f.y;
                acc.z += w * f.z;
                acc.w += w * f.w;
            }

            f0 = g0; f1 = g1; f2 = g2; f3 = g3; sv = sn;
        }

        // final flush of the chunk's last segment
        if (first_inherited) {
            def_acc = acc; def_seg = cur_seg; have_def = true;
        } else {
            *reinterpret_cast<float4*>(
                outp + (long)cur_seg * F_DIM + lane * 4) = acc;
        }
    }

    // ---- grid arrival barrier: all owner stores visible ----
    __threadfence();
    __syncthreads();
    if (threadIdx.x == 0) {
        atomicAdd(&g_arrive, 1);
        while (*((volatile int*)&g_arrive) < total_blocks) { }
    }
    __syncthreads();
    __threadfence();

    // ---- deferred boundary contributions ----
    if (have_def) {
        float* o = outp + (long)def_seg * F_DIM + lane * 4;
        atomicAdd(o + 0, def_acc.x);
        atomicAdd(o + 1, def_acc.y);
        atomicAdd(o + 2, def_acc.z);
        atomicAdd(o + 3, def_acc.w);
    }

    // ---- epilogue: reset counters for the next graph replay ----
    // g_done increments only after this block passed its spin, so the last
    // incrementer implies ALL blocks passed the spin -> safe to reset.
    __syncthreads();
    if (threadIdx.x == 0) {
        int d = atomicAdd(&g_done, 1);
        if (d == total_blocks - 1) {
            g_arrive = 0;
            g_done   = 0;
            __threadfence();
        }
    }
}

extern "C" void kernel_launch(void* const* d_in, const int* in_sizes, int n_in,
                              void* d_out, int out_size)
{
    const float* atom_feats = (const float*)d_in[0];
    const float* vir_feats  = (const float*)d_in[1];
    const float* W_atom     = (const float*)d_in[2];
    const float* b_atom     = (const float*)d_in[3];
    const float* W_vir      = (const float*)d_in[4];
    const float* b_vir      = (const float*)d_in[5];
    const int*   atom_seg   = (const int*)d_in[6];
    const int*   vir_seg    = (const int*)d_in[7];

    const int n_atom = in_sizes[0] / F_DIM;
    const int n_vir  = in_sizes[1] / F_DIM;
    // out layout: [G,128] atom sums | [G,128] vir sums | [n_atom] logits
    const int G = (out_size - n_atom) / (2 * F_DIM);

    float* out       = (float*)d_out;
    float* out_atom  = out;
    float* out_vir   = out + (size_t)G * F_DIM;
    float* logits    = out + (size_t)2 * G * F_DIM;

    // Single wave: 148 SMs * 3 blocks/SM (launch_bounds(256,3)) — required
    // for the in-kernel grid barrier (all blocks co-resident).
    const int threads = 256;
    const int wpb = threads / 32;
    const int total_blocks = 148 * 3;

    long total_rows = (long)n_atom + n_vir;
    int a_blocks = (int)(((long)total_blocks * n_atom + total_rows - 1) / total_rows);
    if (a_blocks < 1) a_blocks = 1;
    if (a_blocks > total_blocks - 1) a_blocks = total_blocks - 1;
    int v_blocks = total_blocks - a_blocks;

    int a_rpw = (n_atom + a_blocks * wpb - 1) / (a_blocks * wpb);
    a_rpw = (a_rpw + 3) & ~3;
    int v_rpw = (n_vir + v_blocks * wpb - 1) / (v_blocks * wpb);
    v_rpw = (v_rpw + 3) & ~3;

    was_kernel<<<total_blocks, threads, 0, 0>>>(
        atom_feats, W_atom, b_atom, atom_seg, out_atom, logits,
        n_atom, a_rpw, a_blocks,
        vir_feats, W_vir, b_vir, vir_seg, out_vir,
        n_vir, v_rpw);
}

// round 9
// speedup vs baseline: 1.2205x; 1.2205x over previous
#include <cuda_runtime.h>
#include <cuda_bf16.h>

// WeightAndSum: gated segment sum. Single-wave persistent layout,
// 4-row groups with depth-2 software pipeline (8 outstanding LDG.128/warp).
//   logits = feats @ W + b   (atom logits output, pre-sigmoid)
//   out[g] = sum_{seg[r]==g} sigmoid(logit_r) * feats[r]
// Sorted segments -> register accumulation, atomic flush on segment change.
// Reduction uses a fold-and-select multi-value butterfly: 13 SHFL per 4 rows
// instead of 20 SHFL + 20 FADD (4 independent butterflies).

#define F_DIM 128
#define F_VEC 32          // float4s per row
#define FULL  0xFFFFFFFFu

__global__ __launch_bounds__(256, 3)
void was_kernel(
    // atom job
    const float* __restrict__ a_feats, const float* __restrict__ a_W,
    const float* __restrict__ a_b, const int* __restrict__ a_seg,
    float* __restrict__ a_out, float* __restrict__ a_logits,
    int a_n, int a_rpw, int a_blocks,
    // vir job
    const float* __restrict__ v_feats, const float* __restrict__ v_W,
    const float* __restrict__ v_b, const int* __restrict__ v_seg,
    float* __restrict__ v_out,
    int v_n, int v_rpw)
{
    const float* feats;
    const float* Wp;
    const float* bp;
    const int*   seg;
    float*       outp;
    float*       logits;
    int n, rpw, block_in_job;

    if (blockIdx.x < (unsigned)a_blocks) {
        feats = a_feats; Wp = a_W; bp = a_b; seg = a_seg;
        outp = a_out; logits = a_logits; n = a_n; rpw = a_rpw;
        block_in_job = blockIdx.x;
    } else {
        feats = v_feats; Wp = v_W; bp = v_b; seg = v_seg;
        outp = v_out; logits = nullptr; n = v_n; rpw = v_rpw;
        block_in_job = blockIdx.x - a_blocks;
    }

    const int lane  = threadIdx.x & 31;
    const int gwarp = block_in_job * (blockDim.x >> 5) + (threadIdx.x >> 5);

    long start = (long)gwarp * rpw;          // rpw is a multiple of 4
    if (start >= n) return;
    long end = start + rpw;
    if (end > n) end = n;                    // n is a multiple of 4

    const float4 Wv  = reinterpret_cast<const float4*>(Wp)[lane];
    const float bias = bp[0];
    const float4* frows = reinterpret_cast<const float4*>(feats);

    const bool lo16 = (lane < 16);
    const bool lo8  = ((lane & 8) == 0);

    float4 acc = make_float4(0.f, 0.f, 0.f, 0.f);
    int cur_seg = __ldg(&seg[start]);

    // ---- depth-2 pipeline: prefetch first 4-row group ----
    float4 f0 = __ldcs(&frows[(start + 0) * F_VEC + lane]);
    float4 f1 = __ldcs(&frows[(start + 1) * F_VEC + lane]);
    float4 f2 = __ldcs(&frows[(start + 2) * F_VEC + lane]);
    float4 f3 = __ldcs(&frows[(start + 3) * F_VEC + lane]);
    int4  sv  = *reinterpret_cast<const int4*>(seg + start);

    for (long r = start; r < end; r += 4) {
        // prefetch next group before consuming current
        float4 g0, g1, g2, g3;
        int4 sn;
        if (r + 4 < end) {
            g0 = __ldcs(&frows[(r + 4) * F_VEC + lane]);
            g1 = __ldcs(&frows[(r + 5) * F_VEC + lane]);
            g2 = __ldcs(&frows[(r + 6) * F_VEC + lane]);
            g3 = __ldcs(&frows[(r + 7) * F_VEC + lane]);
            sn = *reinterpret_cast<const int4*>(seg + r + 4);
        }

        // 4 partial dots
        float p0 = f0.x * Wv.x + f0.y * Wv.y + f0.z * Wv.z + f0.w * Wv.w;
        float p1 = f1.x * Wv.x + f1.y * Wv.y + f1.z * Wv.z + f1.w * Wv.w;
        float p2 = f2.x * Wv.x + f2.y * Wv.y + f2.z * Wv.z + f2.w * Wv.w;
        float p3 = f3.x * Wv.x + f3.y * Wv.y + f3.z * Wv.z + f3.w * Wv.w;

        // fold-and-select multi-value reduction (13 SHFL total)
        p0 += __shfl_xor_sync(FULL, p0, 16);
        p1 += __shfl_xor_sync(FULL, p1, 16);
        p2 += __shfl_xor_sync(FULL, p2, 16);
        p3 += __shfl_xor_sync(FULL, p3, 16);
        float a = lo16 ? p0 : p1;           // lanes 0-15: S0, 16-31: S1
        float b = lo16 ? p2 : p3;           // lanes 0-15: S2, 16-31: S3
        a += __shfl_xor_sync(FULL, a, 8);
        b += __shfl_xor_sync(FULL, b, 8);
        float c = lo8 ? a : b;              // groups: 0-7:S0 8-15:S2 16-23:S1 24-31:S3
        c += __shfl_xor_sync(FULL, c, 4);
        c += __shfl_xor_sync(FULL, c, 2);
        c += __shfl_xor_sync(FULL, c, 1);
        // broadcast the 4 totals
        float l0 = __shfl_sync(FULL, c, 0)  + bias;
        float l1 = __shfl_sync(FULL, c, 16) + bias;
        float l2 = __shfl_sync(FULL, c, 8)  + bias;
        float l3 = __shfl_sync(FULL, c, 24) + bias;

        if (logits != nullptr && lane == 0) {
            __stcs(reinterpret_cast<float4*>(logits + r),
                   make_float4(l0, l1, l2, l3));
        }

        float w0 = 1.0f / (1.0f + __expf(-l0));
        float w1 = 1.0f / (1.0f + __expf(-l1));
        float w2 = 1.0f / (1.0f + __expf(-l2));
        float w3 = 1.0f / (1.0f + __expf(-l3));

        // sequential segment handling (sorted; changes rare)
        #pragma unroll
        for (int k = 0; k < 4; ++k) {
            int s     = (k == 0) ? sv.x : (k == 1) ? sv.y : (k == 2) ? sv.z : sv.w;
            float w   = (k == 0) ? w0   : (k == 1) ? w1   : (k == 2) ? w2   : w3;
            float4 f  = (k == 0) ? f0   : (k == 1) ? f1   : (k == 2) ? f2   : f3;
            if (s != cur_seg) {
                float* o = outp + (long)cur_seg * F_DIM + lane * 4;
                atomicAdd(o + 0, acc.x);
                atomicAdd(o + 1, acc.y);
                atomicAdd(o + 2, acc.z);
                atomicAdd(o + 3, acc.w);
                acc = make_float4(0.f, 0.f, 0.f, 0.f);
                cur_seg = s;
            }
            acc.x += w * f.x;
            acc.y += w * f.y;
            acc.z += w * f.z;
            acc.w += w * f.w;
        }

        f0 = g0; f1 = g1; f2 = g2; f3 = g3; sv = sn;
    }

    // final flush
    float* o = outp + (long)cur_seg * F_DIM + lane * 4;
    atomicAdd(o + 0, acc.x);
    atomicAdd(o + 1, acc.y);
    atomicAdd(o + 2, acc.z);
    atomicAdd(o + 3, acc.w);
}

extern "C" void kernel_launch(void* const* d_in, const int* in_sizes, int n_in,
                              void* d_out, int out_size)
{
    const float* atom_feats = (const float*)d_in[0];
    const float* vir_feats  = (const float*)d_in[1];
    const float* W_atom     = (const float*)d_in[2];
    const float* b_atom     = (const float*)d_in[3];
    const float* W_vir      = (const float*)d_in[4];
    const float* b_vir      = (const float*)d_in[5];
    const int*   atom_seg   = (const int*)d_in[6];
    const int*   vir_seg    = (const int*)d_in[7];

    const int n_atom = in_sizes[0] / F_DIM;
    const int n_vir  = in_sizes[1] / F_DIM;
    // out layout: [G,128] atom sums | [G,128] vir sums | [n_atom] logits
    const int G = (out_size - n_atom) / (2 * F_DIM);

    float* out       = (float*)d_out;
    float* out_atom  = out;
    float* out_vir   = out + (size_t)G * F_DIM;
    float* logits    = out + (size_t)2 * G * F_DIM;

    cudaMemsetAsync(out, 0, (size_t)2 * G * F_DIM * sizeof(float), 0);

    // Single wave: 148 SMs * 3 blocks/SM (launch_bounds(256,3))
    const int threads = 256;
    const int wpb = threads / 32;
    const int total_blocks = 148 * 3;

    long total_rows = (long)n_atom + n_vir;
    int a_blocks = (int)(((long)total_blocks * n_atom + total_rows - 1) / total_rows);
    if (a_blocks < 1) a_blocks = 1;
    if (a_blocks > total_blocks - 1) a_blocks = total_blocks - 1;
    int v_blocks = total_blocks - a_blocks;

    int a_rpw = (n_atom + a_blocks * wpb - 1) / (a_blocks * wpb);
    a_rpw = (a_rpw + 3) & ~3;
    int v_rpw = (n_vir + v_blocks * wpb - 1) / (v_blocks * wpb);
    v_rpw = (v_rpw + 3) & ~3;

    was_kernel<<<total_blocks, threads, 0, 0>>>(
        atom_feats, W_atom, b_atom, atom_seg, out_atom, logits,
        n_atom, a_rpw, a_blocks,
        vir_feats, W_vir, b_vir, vir_seg, out_vir,
        n_vir, v_rpw);
}